// round 15
// baseline (speedup 1.0000x reference)
#include <cuda_runtime.h>
#include <cstdint>

// LSTMDecoder: B=1024, A=H=16, R=128, T=128.
// R14: TLP via co-residency. Cell identical in spirit to R5/R8 (best): scalar
// FFMA gate dots (even/odd split), sync-free SMEM h broadcast, tanh.approx
// MUFU tail with folded 0.5 sigmoid scaling. The change: 64 blocks x 256
// threads -> 8 warps/SM on 64 SMs = 2 warps per SMSP. Two independent LSTM
// chains per scheduler hide each other's dependency stalls; throughput moves
// from chain-latency-bound (~196 cyc/cell) to fma-pipe-floor (~128 cyc/cell).
// Scalar FFMA (not f32x2): 64 x rt2 = 128 pipe-cyc < 36 x rt4 = 144 (R12
// measured FFMA2 at rt~4).

#define NT 128

__device__ __forceinline__ float tanhapx(float x) {
    float r;
    asm("tanh.approx.f32 %0, %1;" : "=f"(r) : "f"(x));
    return r;
}

__global__ __launch_bounds__(256, 1)
void lstm_decoder_kernel(
    const float* __restrict__ y,     // (B,16)
    const float* __restrict__ u,     // (B,128)
    const float* __restrict__ W_ih,  // (64,1)
    const float* __restrict__ W_hh,  // (64,16)
    const float* __restrict__ b_ih,  // (64)
    const float* __restrict__ b_hh,  // (64)
    const float* __restrict__ W_lin, // (1,16)
    const float* __restrict__ b_lin, // (1)
    const float* __restrict__ W_h0,  // (16,128)
    const float* __restrict__ b_h0,  // (16)
    const float* __restrict__ W_c0,  // (16,128)
    const float* __restrict__ b_c0,  // (16)
    float* __restrict__ out)         // (B,144)
{
    const int tid = blockIdx.x * 256 + threadIdx.x;
    const int b   = tid >> 4;     // batch element
    const int j   = tid & 15;     // hidden index
    const unsigned FULL = 0xffffffffu;

    // shared h: 16 batch slots per block x 16 floats
    __shared__ __align__(16) float sh[16 * 16];
    uint32_t sbase;
    asm("{ .reg .u64 t; cvta.to.shared.u64 t, %1; cvt.u32.u64 %0, t; }"
        : "=r"(sbase) : "l"(sh));
    const int bb = threadIdx.x >> 4;              // batch slot in block
    const uint32_t rdaddr = sbase + bb * 64;      // slot base (16 floats)
    const uint32_t wraddr = rdaddr + j * 4;       // this lane's h slot

    // ---- per-thread weights: 4 gate rows of W_hh ----
    // i,f,o rows pre-scaled by 0.5 (sigmoid folding); g unscaled.
    float Wi[16], Wf[16], Wg[16], Wo[16];
#pragma unroll
    for (int k = 0; k < 16; k++) {
        Wi[k] = 0.5f * W_hh[(     j) * 16 + k];
        Wf[k] = 0.5f * W_hh[(16 + j) * 16 + k];
        Wg[k] =        W_hh[(32 + j) * 16 + k];
        Wo[k] = 0.5f * W_hh[(48 + j) * 16 + k];
    }
    const float wxi = 0.5f * W_ih[j];
    const float wxf = 0.5f * W_ih[16 + j];
    const float wxg =        W_ih[32 + j];
    const float wxo = 0.5f * W_ih[48 + j];
    const float bvi = 0.5f * (b_ih[j]      + b_hh[j]);
    const float bvf = 0.5f * (b_ih[16 + j] + b_hh[16 + j]);
    const float bvg =        (b_ih[32 + j] + b_hh[32 + j]);
    const float bvo = 0.5f * (b_ih[48 + j] + b_hh[48 + j]);
    const float wl = W_lin[j];
    const float bl = b_lin[0];

    // ---- h0 = u @ W_h0.T + b_h0 ; c0 = u @ W_c0.T + b_c0 ----
    float h = b_h0[j];
    float c = b_c0[j];
    {
        const float4* u4  = (const float4*)(u    + b * 128);
        const float4* wh4 = (const float4*)(W_h0 + j * 128);
        const float4* wc4 = (const float4*)(W_c0 + j * 128);
#pragma unroll 4
        for (int r = 0; r < 32; r++) {
            float4 uu = u4[r], wh = wh4[r], wc = wc4[r];
            h = fmaf(uu.x, wh.x, h); h = fmaf(uu.y, wh.y, h);
            h = fmaf(uu.z, wh.z, h); h = fmaf(uu.w, wh.w, h);
            c = fmaf(uu.x, wc.x, c); c = fmaf(uu.y, wc.y, c);
            c = fmaf(uu.z, wc.z, c); c = fmaf(uu.w, wc.w, c);
        }
    }

    // ---- window replicated per-thread: xs[s] = window[:, s] ----
    float xs[16];
    {
        const float4* y4 = (const float4*)(y + b * 16);
#pragma unroll
        for (int q = 0; q < 4; q++) {
            float4 v = y4[q];
            xs[4*q] = v.x; xs[4*q+1] = v.y; xs[4*q+2] = v.z; xs[4*q+3] = v.w;
        }
    }
    out[b * 144 + j] = y[b * 16 + j];        // first 16 output cols = y
    float* outp = out + b * 144 + 16;

#pragma unroll 1
    for (int t = 0; t < NT; t++) {
#pragma unroll
        for (int s = 0; s < 16; s++) {
            // publish h (warp-wide STS; per-warp in-order MIO => visible to
            // the LDS below without syncwarp in convergent code)
            asm volatile("st.shared.f32 [%0], %1;" :: "r"(wraddr), "f"(h) : "memory");

            float xv = xs[s];
            float ai0 = fmaf(xv, wxi, bvi), ai1 = 0.0f;
            float af0 = fmaf(xv, wxf, bvf), af1 = 0.0f;
            float ag0 = fmaf(xv, wxg, bvg), ag1 = 0.0f;
            float ao0 = fmaf(xv, wxo, bvo), ao1 = 0.0f;

            float hv0, hv1, hv2, hv3, hv4, hv5, hv6, hv7;
            float hv8, hv9, hva, hvb, hvc, hvd, hve, hvf;
            asm volatile("ld.shared.v4.f32 {%0,%1,%2,%3}, [%4];"
                         : "=f"(hv0), "=f"(hv1), "=f"(hv2), "=f"(hv3)
                         : "r"(rdaddr) : "memory");
            asm volatile("ld.shared.v4.f32 {%0,%1,%2,%3}, [%4];"
                         : "=f"(hv4), "=f"(hv5), "=f"(hv6), "=f"(hv7)
                         : "r"(rdaddr + 16) : "memory");
            asm volatile("ld.shared.v4.f32 {%0,%1,%2,%3}, [%4];"
                         : "=f"(hv8), "=f"(hv9), "=f"(hva), "=f"(hvb)
                         : "r"(rdaddr + 32) : "memory");
            asm volatile("ld.shared.v4.f32 {%0,%1,%2,%3}, [%4];"
                         : "=f"(hvc), "=f"(hvd), "=f"(hve), "=f"(hvf)
                         : "r"(rdaddr + 48) : "memory");

            // even/odd split scalar FFMA chains (depth 8 each)
            ai0 = fmaf(hv0, Wi[0], ai0);   ai1 = fmaf(hv1, Wi[1], ai1);
            ag0 = fmaf(hv0, Wg[0], ag0);   ag1 = fmaf(hv1, Wg[1], ag1);
            af0 = fmaf(hv0, Wf[0], af0);   af1 = fmaf(hv1, Wf[1], af1);
            ao0 = fmaf(hv0, Wo[0], ao0);   ao1 = fmaf(hv1, Wo[1], ao1);
            ai0 = fmaf(hv2, Wi[2], ai0);   ai1 = fmaf(hv3, Wi[3], ai1);
            ag0 = fmaf(hv2, Wg[2], ag0);   ag1 = fmaf(hv3, Wg[3], ag1);
            af0 = fmaf(hv2, Wf[2], af0);   af1 = fmaf(hv3, Wf[3], af1);
            ao0 = fmaf(hv2, Wo[2], ao0);   ao1 = fmaf(hv3, Wo[3], ao1);
            ai0 = fmaf(hv4, Wi[4], ai0);   ai1 = fmaf(hv5, Wi[5], ai1);
            ag0 = fmaf(hv4, Wg[4], ag0);   ag1 = fmaf(hv5, Wg[5], ag1);
            af0 = fmaf(hv4, Wf[4], af0);   af1 = fmaf(hv5, Wf[5], af1);
            ao0 = fmaf(hv4, Wo[4], ao0);   ao1 = fmaf(hv5, Wo[5], ao1);
            ai0 = fmaf(hv6, Wi[6], ai0);   ai1 = fmaf(hv7, Wi[7], ai1);
            ag0 = fmaf(hv6, Wg[6], ag0);   ag1 = fmaf(hv7, Wg[7], ag1);
            af0 = fmaf(hv6, Wf[6], af0);   af1 = fmaf(hv7, Wf[7], af1);
            ao0 = fmaf(hv6, Wo[6], ao0);   ao1 = fmaf(hv7, Wo[7], ao1);
            ai0 = fmaf(hv8, Wi[8], ai0);   ai1 = fmaf(hv9, Wi[9], ai1);
            ag0 = fmaf(hv8, Wg[8], ag0);   ag1 = fmaf(hv9, Wg[9], ag1);
            af0 = fmaf(hv8, Wf[8], af0);   af1 = fmaf(hv9, Wf[9], af1);
            ao0 = fmaf(hv8, Wo[8], ao0);   ao1 = fmaf(hv9, Wo[9], ao1);
            ai0 = fmaf(hva, Wi[10], ai0);  ai1 = fmaf(hvb, Wi[11], ai1);
            ag0 = fmaf(hva, Wg[10], ag0);  ag1 = fmaf(hvb, Wg[11], ag1);
            af0 = fmaf(hva, Wf[10], af0);  af1 = fmaf(hvb, Wf[11], af1);
            ao0 = fmaf(hva, Wo[10], ao0);  ao1 = fmaf(hvb, Wo[11], ao1);
            ai0 = fmaf(hvc, Wi[12], ai0);  ai1 = fmaf(hvd, Wi[13], ai1);
            ag0 = fmaf(hvc, Wg[12], ag0);  ag1 = fmaf(hvd, Wg[13], ag1);
            af0 = fmaf(hvc, Wf[12], af0);  af1 = fmaf(hvd, Wf[13], af1);
            ao0 = fmaf(hvc, Wo[12], ao0);  ao1 = fmaf(hvd, Wo[13], ao1);
            ai0 = fmaf(hve, Wi[14], ai0);  ai1 = fmaf(hvf, Wi[15], ai1);
            ag0 = fmaf(hve, Wg[14], ag0);  ag1 = fmaf(hvf, Wg[15], ag1);
            af0 = fmaf(hve, Wf[14], af0);  af1 = fmaf(hvf, Wf[15], af1);
            ao0 = fmaf(hve, Wo[14], ao0);  ao1 = fmaf(hvf, Wo[15], ao1);

            // g first (product with i feeds c-fma), f next (multiplies c)
            float gg = tanhapx(ag0 + ag1);
            float ig = fmaf(0.5f, tanhapx(ai0 + ai1), 0.5f);
            float fg = fmaf(0.5f, tanhapx(af0 + af1), 0.5f);
            float og = fmaf(0.5f, tanhapx(ao0 + ao1), 0.5f);
            c = fmaf(fg, c, ig * gg);
            h = og * tanhapx(c);
        }
        // pred = sum_j h_j * W_lin_j + b_lin (feeds xs[15], consumed 15 cells
        // later)
        float p = h * wl;
#pragma unroll
        for (int off = 8; off; off >>= 1)
            p += __shfl_xor_sync(FULL, p, off, 16);
        p += bl;

        if (j == 0) outp[t] = p;

#pragma unroll
        for (int s = 0; s < 15; s++) xs[s] = xs[s + 1];
        xs[15] = p;
    }
}

extern "C" void kernel_launch(void* const* d_in, const int* in_sizes, int n_in,
                              void* d_out, int out_size) {
    const float* y     = (const float*)d_in[0];
    const float* u     = (const float*)d_in[1];
    const float* W_ih  = (const float*)d_in[2];
    const float* W_hh  = (const float*)d_in[3];
    const float* b_ih  = (const float*)d_in[4];
    const float* b_hh  = (const float*)d_in[5];
    const float* W_lin = (const float*)d_in[6];
    const float* b_lin = (const float*)d_in[7];
    const float* W_h0  = (const float*)d_in[8];
    const float* b_h0  = (const float*)d_in[9];
    const float* W_c0  = (const float*)d_in[10];
    const float* b_c0  = (const float*)d_in[11];
    float* out = (float*)d_out;

    // 64 blocks x 256 threads = 16384 threads; 8 warps/SM on 64 SMs
    // -> 2 co-resident warps per SMSP (TLP hides per-warp chain stalls)
    lstm_decoder_kernel<<<64, 256>>>(y, u, W_ih, W_hh, b_ih, b_hh,
                                     W_lin, b_lin, W_h0, b_h0, W_c0, b_c0, out);
}

// round 16
// speedup vs baseline: 1.0807x; 1.0807x over previous
#include <cuda_runtime.h>
#include <cstdint>

// LSTMDecoder: B=1024, A=H=16, R=128, T=128.
// R15: gate-split (32 lanes per cell) + batch-pair alternation per warp.
//   Warp owns batches bA, bB. Per cell, all 32 lanes work on ONE batch:
//   lane (p, j): p=0 computes gate rows i,f of hidden j; p=1 computes g,o.
//   32 scalar FFMA/lane/cell -> fma-issue span 64 cyc/cell (was 128).
//   Cells of A and B alternate in program order; A's MUFU tail issues under
//   B's FFMA dot (different pipes, independent chains) -> tail hidden.
//   Halves exchange raw gate sums via 2 shfl_xor(16) (hidden under the other
//   batch's dot); both halves run the tail redundantly (no divergence).
// 512 warps = 128 blocks x 128 threads, 1 warp/SMSP (max spread, R5-optimal).
// Broadcast: sync-free SMEM STS->LDS.128 (validated R8). Sigmoid 0.5-scale
// folded into i,f,o weights/biases. Scalar FFMA only (FFMA2 measured rt~4).

#define NT 128
#define FULLM 0xffffffffu

__device__ __forceinline__ float tanhapx(float x) {
    float r;
    asm("tanh.approx.f32 %0, %1;" : "=f"(r) : "f"(x));
    return r;
}

// ---- one batch's dot (32 FFMA, even/odd split per row) ----
#define DOT32(S0E, S0O, S1E, S1O, H0,H1,H2,H3,H4,H5,H6,H7,H8,H9,HA,HB,HC,HD,HE,HF) \
    S0E = fmaf(H0, W0[0],  S0E);  S0O = fmaf(H1, W0[1],  S0O);                \
    S1E = fmaf(H0, W1[0],  S1E);  S1O = fmaf(H1, W1[1],  S1O);                \
    S0E = fmaf(H2, W0[2],  S0E);  S0O = fmaf(H3, W0[3],  S0O);                \
    S1E = fmaf(H2, W1[2],  S1E);  S1O = fmaf(H3, W1[3],  S1O);                \
    S0E = fmaf(H4, W0[4],  S0E);  S0O = fmaf(H5, W0[5],  S0O);                \
    S1E = fmaf(H4, W1[4],  S1E);  S1O = fmaf(H5, W1[5],  S1O);                \
    S0E = fmaf(H6, W0[6],  S0E);  S0O = fmaf(H7, W0[7],  S0O);                \
    S1E = fmaf(H6, W1[6],  S1E);  S1O = fmaf(H7, W1[7],  S1O);                \
    S0E = fmaf(H8, W0[8],  S0E);  S0O = fmaf(H9, W0[9],  S0O);                \
    S1E = fmaf(H8, W1[8],  S1E);  S1O = fmaf(H9, W1[9],  S1O);                \
    S0E = fmaf(HA, W0[10], S0E);  S0O = fmaf(HB, W0[11], S0O);                \
    S1E = fmaf(HA, W1[10], S1E);  S1O = fmaf(HB, W1[11], S1O);                \
    S0E = fmaf(HC, W0[12], S0E);  S0O = fmaf(HD, W0[13], S0O);                \
    S1E = fmaf(HC, W1[12], S1E);  S1O = fmaf(HD, W1[13], S1O);                \
    S0E = fmaf(HE, W0[14], S0E);  S0O = fmaf(HF, W0[15], S0O);                \
    S1E = fmaf(HE, W1[14], S1E);  S1O = fmaf(HF, W1[15], S1O)

#define LDS16(RD, H0,H1,H2,H3,H4,H5,H6,H7,H8,H9,HA,HB,HC,HD,HE,HF)            \
    asm volatile("ld.shared.v4.f32 {%0,%1,%2,%3}, [%4];"                      \
                 : "=f"(H0), "=f"(H1), "=f"(H2), "=f"(H3) : "r"(RD) : "memory"); \
    asm volatile("ld.shared.v4.f32 {%0,%1,%2,%3}, [%4];"                      \
                 : "=f"(H4), "=f"(H5), "=f"(H6), "=f"(H7) : "r"(RD+16) : "memory"); \
    asm volatile("ld.shared.v4.f32 {%0,%1,%2,%3}, [%4];"                      \
                 : "=f"(H8), "=f"(H9), "=f"(HA), "=f"(HB) : "r"(RD+32) : "memory"); \
    asm volatile("ld.shared.v4.f32 {%0,%1,%2,%3}, [%4];"                      \
                 : "=f"(HC), "=f"(HD), "=f"(HE), "=f"(HF) : "r"(RD+48) : "memory")

// tail from exchanged sums (both halves redundant)
#define TAIL(SUM0, O0, SUM1, O1, CV, HV) do {                                 \
    float hai_ = p ? (O0) : (SUM0);      /* 0.5*ai */                         \
    float agf_ = p ? (SUM0) : (O0);      /* ag */                             \
    float haf_ = p ? (O1) : (SUM1);      /* 0.5*af */                         \
    float hao_ = p ? (SUM1) : (O1);      /* 0.5*ao */                         \
    float gg_ = tanhapx(agf_);                                                \
    float ig_ = fmaf(0.5f, tanhapx(hai_), 0.5f);                              \
    float fg_ = fmaf(0.5f, tanhapx(haf_), 0.5f);                              \
    float og_ = fmaf(0.5f, tanhapx(hao_), 0.5f);                              \
    CV = fmaf(fg_, CV, ig_ * gg_);                                            \
    HV = og_ * tanhapx(CV);                                                   \
} while (0)

// one cell-pair: cell s of batch A and of batch B, interleaved
#define CELLPAIR(XA, XB) do {                                                 \
    asm volatile("st.shared.f32 [%0], %1;" :: "r"(wrA), "f"(hA) : "memory");  \
    asm volatile("st.shared.f32 [%0], %1;" :: "r"(wrB), "f"(hB) : "memory");  \
    float a0Ae = fmaf((XA), wx0, bv0), a0Ao = 0.0f;                           \
    float a1Ae = fmaf((XA), wx1, bv1), a1Ao = 0.0f;                           \
    float a0Be = fmaf((XB), wx0, bv0), a0Bo = 0.0f;                           \
    float a1Be = fmaf((XB), wx1, bv1), a1Bo = 0.0f;                           \
    float gA0,gA1,gA2,gA3,gA4,gA5,gA6,gA7,gA8,gA9,gAa,gAb,gAc,gAd,gAe,gAf;    \
    LDS16(rdA, gA0,gA1,gA2,gA3,gA4,gA5,gA6,gA7,gA8,gA9,gAa,gAb,gAc,gAd,gAe,gAf); \
    DOT32(a0Ae,a0Ao,a1Ae,a1Ao, gA0,gA1,gA2,gA3,gA4,gA5,gA6,gA7,               \
          gA8,gA9,gAa,gAb,gAc,gAd,gAe,gAf);                                   \
    float sA0 = a0Ae + a0Ao, sA1 = a1Ae + a1Ao;                               \
    float oA0 = __shfl_xor_sync(FULLM, sA0, 16);                              \
    float oA1 = __shfl_xor_sync(FULLM, sA1, 16);                              \
    float gB0,gB1,gB2,gB3,gB4,gB5,gB6,gB7,gB8,gB9,gBa,gBb,gBc,gBd,gBe,gBf;    \
    LDS16(rdB, gB0,gB1,gB2,gB3,gB4,gB5,gB6,gB7,gB8,gB9,gBa,gBb,gBc,gBd,gBe,gBf); \
    DOT32(a0Be,a0Bo,a1Be,a1Bo, gB0,gB1,gB2,gB3,gB4,gB5,gB6,gB7,               \
          gB8,gB9,gBa,gBb,gBc,gBd,gBe,gBf);                                   \
    TAIL(sA0, oA0, sA1, oA1, cA, hA);                                         \
    float sB0 = a0Be + a0Bo, sB1 = a1Be + a1Bo;                               \
    float oB0 = __shfl_xor_sync(FULLM, sB0, 16);                              \
    float oB1 = __shfl_xor_sync(FULLM, sB1, 16);                              \
    TAIL(sB0, oB0, sB1, oB1, cB, hB);                                         \
} while (0)

__global__ __launch_bounds__(128, 1)
void lstm_decoder_kernel(
    const float* __restrict__ y,     // (B,16)
    const float* __restrict__ u,     // (B,128)
    const float* __restrict__ W_ih,  // (64,1)
    const float* __restrict__ W_hh,  // (64,16)
    const float* __restrict__ b_ih,  // (64)
    const float* __restrict__ b_hh,  // (64)
    const float* __restrict__ W_lin, // (1,16)
    const float* __restrict__ b_lin, // (1)
    const float* __restrict__ W_h0,  // (16,128)
    const float* __restrict__ b_h0,  // (16)
    const float* __restrict__ W_c0,  // (16,128)
    const float* __restrict__ b_c0,  // (16)
    float* __restrict__ out)         // (B,144)
{
    const int lane = threadIdx.x & 31;
    const int wid  = threadIdx.x >> 5;                 // warp in block (0..3)
    const int gw   = blockIdx.x * 4 + wid;             // global warp (0..511)
    const int bA   = gw * 2;                           // batch A
    const int bB   = gw * 2 + 1;                       // batch B
    const int p    = lane >> 4;                        // gate-half
    const int j    = lane & 15;                        // hidden index

    // shared h: 4 warps x 2 batches x 16 floats
    __shared__ __align__(16) float sh[4 * 2 * 16];
    uint32_t sbase;
    asm("{ .reg .u64 t; cvta.to.shared.u64 t, %1; cvt.u32.u64 %0, t; }"
        : "=r"(sbase) : "l"(sh));
    const uint32_t rdA = sbase + wid * 128;
    const uint32_t rdB = rdA + 64;
    const uint32_t wrA = rdA + j * 4;   // both halves write same value: benign
    const uint32_t wrB = rdB + j * 4;

    // ---- per-lane weights: 2 gate rows of W_hh ----
    // p=0: rows (i=j, f=16+j), scale 0.5 both (sigmoid folding)
    // p=1: rows (g=32+j scale 1, o=48+j scale 0.5)
    const int r0 = p ? (32 + j) : j;
    const int r1 = p ? (48 + j) : (16 + j);
    const float s0 = p ? 1.0f : 0.5f;

    float W0[16], W1[16];
#pragma unroll
    for (int k = 0; k < 16; k++) {
        W0[k] = s0   * W_hh[r0 * 16 + k];
        W1[k] = 0.5f * W_hh[r1 * 16 + k];
    }
    const float wx0 = s0   * W_ih[r0];
    const float wx1 = 0.5f * W_ih[r1];
    const float bv0 = s0   * (b_ih[r0] + b_hh[r0]);
    const float bv1 = 0.5f * (b_ih[r1] + b_hh[r1]);
    const float wl = W_lin[j];
    const float bl = b_lin[0];

    // ---- h0/c0 for both batches (redundant across halves; 4 dot chains) ----
    float hA = b_h0[j], cA = b_c0[j];
    float hB = hA,      cB = cA;
    {
        const float4* uA4 = (const float4*)(u    + bA * 128);
        const float4* uB4 = (const float4*)(u    + bB * 128);
        const float4* wh4 = (const float4*)(W_h0 + j * 128);
        const float4* wc4 = (const float4*)(W_c0 + j * 128);
#pragma unroll 4
        for (int r = 0; r < 32; r++) {
            float4 ua = uA4[r], ub = uB4[r], wh = wh4[r], wc = wc4[r];
            hA = fmaf(ua.x, wh.x, hA); hA = fmaf(ua.y, wh.y, hA);
            hA = fmaf(ua.z, wh.z, hA); hA = fmaf(ua.w, wh.w, hA);
            cA = fmaf(ua.x, wc.x, cA); cA = fmaf(ua.y, wc.y, cA);
            cA = fmaf(ua.z, wc.z, cA); cA = fmaf(ua.w, wc.w, cA);
            hB = fmaf(ub.x, wh.x, hB); hB = fmaf(ub.y, wh.y, hB);
            hB = fmaf(ub.z, wh.z, hB); hB = fmaf(ub.w, wh.w, hB);
            cB = fmaf(ub.x, wc.x, cB); cB = fmaf(ub.y, wc.y, cB);
            cB = fmaf(ub.z, wc.z, cB); cB = fmaf(ub.w, wc.w, cB);
        }
    }

    // ---- windows replicated on all 32 lanes ----
    float xsA[16], xsB[16];
    {
        const float4* yA4 = (const float4*)(y + bA * 16);
        const float4* yB4 = (const float4*)(y + bB * 16);
#pragma unroll
        for (int q = 0; q < 4; q++) {
            float4 va = yA4[q], vb = yB4[q];
            xsA[4*q]=va.x; xsA[4*q+1]=va.y; xsA[4*q+2]=va.z; xsA[4*q+3]=va.w;
            xsB[4*q]=vb.x; xsB[4*q+1]=vb.y; xsB[4*q+2]=vb.z; xsB[4*q+3]=vb.w;
        }
    }
    if (p == 0) {
        out[bA * 144 + j] = xsA[j & 15] * 0.0f + y[bA * 16 + j];
        out[bB * 144 + j] = y[bB * 16 + j];
    }
    float* outA = out + bA * 144 + 16;
    float* outB = out + bB * 144 + 16;

#pragma unroll 1
    for (int t = 0; t < NT; t++) {
#pragma unroll
        for (int s = 0; s < 16; s++) {
            CELLPAIR(xsA[s], xsB[s]);
        }
        // preds for both batches (h on all 32 lanes; width-16 butterflies)
        float pA = hA * wl, pB = hB * wl;
#pragma unroll
        for (int off = 8; off; off >>= 1) {
            pA += __shfl_xor_sync(FULLM, pA, off, 16);
            pB += __shfl_xor_sync(FULLM, pB, off, 16);
        }
        pA += bl; pB += bl;
        if (lane == 0) outA[t] = pA;
        if (lane == 16) outB[t] = pB;
#pragma unroll
        for (int s = 0; s < 15; s++) { xsA[s] = xsA[s + 1]; xsB[s] = xsB[s + 1]; }
        xsA[15] = pA; xsB[15] = pB;
    }
}

extern "C" void kernel_launch(void* const* d_in, const int* in_sizes, int n_in,
                              void* d_out, int out_size) {
    const float* y     = (const float*)d_in[0];
    const float* u     = (const float*)d_in[1];
    const float* W_ih  = (const float*)d_in[2];
    const float* W_hh  = (const float*)d_in[3];
    const float* b_ih  = (const float*)d_in[4];
    const float* b_hh  = (const float*)d_in[5];
    const float* W_lin = (const float*)d_in[6];
    const float* b_lin = (const float*)d_in[7];
    const float* W_h0  = (const float*)d_in[8];
    const float* b_h0  = (const float*)d_in[9];
    const float* W_c0  = (const float*)d_in[10];
    const float* b_c0  = (const float*)d_in[11];
    float* out = (float*)d_out;

    // 128 blocks x 128 threads = 512 warps, 1/SMSP over 128 SMs;
    // each warp: 2 batches, 32 lanes per cell, cells alternate A/B.
    lstm_decoder_kernel<<<128, 128>>>(y, u, W_ih, W_hh, b_ih, b_hh,
                                      W_lin, b_lin, W_h0, b_h0, W_c0, b_c0, out);
}

// round 17
// speedup vs baseline: 1.5149x; 1.4018x over previous
#include <cuda_runtime.h>
#include <cstdint>

// LSTMDecoder: B=1024, A=H=16, R=128, T=128.
// R16: critical-cycle scheduling inside the R5-best cell.
//   Model (validated R5..R15): wallclock = single-warp per-cell time; layout
//   2 batches/warp SIMD (16 lanes each), 1 warp/SMSP, 64 scalar FFMA/lane is
//   the optimal decomposition; 196 cyc/cell = bcast + 128-cyc fma span with
//   the tail exposed after it.
//   Change: f-gate dot completes FIRST (4-way split, depth 5) so sigmoid(af)
//   -> c-fma run UNDER the i/g/o FFMA span; o-gate dot issued LAST so og
//   arrives just in time for h = og*tanh(c). Only tanh(c)+mul stay exposed.
// Broadcast: sync-free SMEM STS->LDS.128 (validated R8). Sigmoid 0.5-scale
// folded into i,f,o weights/biases. Scalar FFMA only (FFMA2 measured rt~4).

#define NT 128

__device__ __forceinline__ float tanhapx(float x) {
    float r;
    asm("tanh.approx.f32 %0, %1;" : "=f"(r) : "f"(x));
    return r;
}

__global__ __launch_bounds__(128, 1)
void lstm_decoder_kernel(
    const float* __restrict__ y,     // (B,16)
    const float* __restrict__ u,     // (B,128)
    const float* __restrict__ W_ih,  // (64,1)
    const float* __restrict__ W_hh,  // (64,16)
    const float* __restrict__ b_ih,  // (64)
    const float* __restrict__ b_hh,  // (64)
    const float* __restrict__ W_lin, // (1,16)
    const float* __restrict__ b_lin, // (1)
    const float* __restrict__ W_h0,  // (16,128)
    const float* __restrict__ b_h0,  // (16)
    const float* __restrict__ W_c0,  // (16,128)
    const float* __restrict__ b_c0,  // (16)
    float* __restrict__ out)         // (B,144)
{
    const int tid = blockIdx.x * 128 + threadIdx.x;
    const int b   = tid >> 4;     // batch element
    const int j   = tid & 15;     // hidden index
    const unsigned FULL = 0xffffffffu;

    // shared h: 8 batch slots per block x 16 floats
    __shared__ __align__(16) float sh[8 * 16];
    uint32_t sbase;
    asm("{ .reg .u64 t; cvta.to.shared.u64 t, %1; cvt.u32.u64 %0, t; }"
        : "=r"(sbase) : "l"(sh));
    const int bb = threadIdx.x >> 4;              // batch slot in block
    const uint32_t rdaddr = sbase + bb * 64;      // slot base (16 floats)
    const uint32_t wraddr = rdaddr + j * 4;       // this lane's h slot

    // ---- per-thread weights: 4 gate rows of W_hh ----
    // i,f,o rows pre-scaled by 0.5 (sigmoid folding); g unscaled.
    float Wi[16], Wf[16], Wg[16], Wo[16];
#pragma unroll
    for (int k = 0; k < 16; k++) {
        Wi[k] = 0.5f * W_hh[(     j) * 16 + k];
        Wf[k] = 0.5f * W_hh[(16 + j) * 16 + k];
        Wg[k] =        W_hh[(32 + j) * 16 + k];
        Wo[k] = 0.5f * W_hh[(48 + j) * 16 + k];
    }
    const float wxi = 0.5f * W_ih[j];
    const float wxf = 0.5f * W_ih[16 + j];
    const float wxg =        W_ih[32 + j];
    const float wxo = 0.5f * W_ih[48 + j];
    const float bvi = 0.5f * (b_ih[j]      + b_hh[j]);
    const float bvf = 0.5f * (b_ih[16 + j] + b_hh[16 + j]);
    const float bvg =        (b_ih[32 + j] + b_hh[32 + j]);
    const float bvo = 0.5f * (b_ih[48 + j] + b_hh[48 + j]);
    const float wl = W_lin[j];
    const float bl = b_lin[0];

    // ---- h0 = u @ W_h0.T + b_h0 ; c0 = u @ W_c0.T + b_c0 ----
    float h = b_h0[j];
    float c = b_c0[j];
    {
        const float4* u4  = (const float4*)(u    + b * 128);
        const float4* wh4 = (const float4*)(W_h0 + j * 128);
        const float4* wc4 = (const float4*)(W_c0 + j * 128);
#pragma unroll 4
        for (int r = 0; r < 32; r++) {
            float4 uu = u4[r], wh = wh4[r], wc = wc4[r];
            h = fmaf(uu.x, wh.x, h); h = fmaf(uu.y, wh.y, h);
            h = fmaf(uu.z, wh.z, h); h = fmaf(uu.w, wh.w, h);
            c = fmaf(uu.x, wc.x, c); c = fmaf(uu.y, wc.y, c);
            c = fmaf(uu.z, wc.z, c); c = fmaf(uu.w, wc.w, c);
        }
    }

    // ---- window replicated per-thread: xs[s] = window[:, s] ----
    float xs[16];
    {
        const float4* y4 = (const float4*)(y + b * 16);
#pragma unroll
        for (int q = 0; q < 4; q++) {
            float4 v = y4[q];
            xs[4*q] = v.x; xs[4*q+1] = v.y; xs[4*q+2] = v.z; xs[4*q+3] = v.w;
        }
    }
    out[b * 144 + j] = y[b * 16 + j];        // first 16 output cols = y
    float* outp = out + b * 144 + 16;

#pragma unroll 1
    for (int t = 0; t < NT; t++) {
#pragma unroll
        for (int s = 0; s < 16; s++) {
            // publish h (warp-wide STS; per-warp in-order MIO => visible to
            // the LDS below without syncwarp in convergent code)
            asm volatile("st.shared.f32 [%0], %1;" :: "r"(wraddr), "f"(h) : "memory");

            float xv = xs[s];
            float hv0, hv1, hv2, hv3, hv4, hv5, hv6, hv7;
            float hv8, hv9, hva, hvb, hvc, hvd, hve, hvf;
            asm volatile("ld.shared.v4.f32 {%0,%1,%2,%3}, [%4];"
                         : "=f"(hv0), "=f"(hv1), "=f"(hv2), "=f"(hv3)
                         : "r"(rdaddr) : "memory");
            asm volatile("ld.shared.v4.f32 {%0,%1,%2,%3}, [%4];"
                         : "=f"(hv4), "=f"(hv5), "=f"(hv6), "=f"(hv7)
                         : "r"(rdaddr + 16) : "memory");
            asm volatile("ld.shared.v4.f32 {%0,%1,%2,%3}, [%4];"
                         : "=f"(hv8), "=f"(hv9), "=f"(hva), "=f"(hvb)
                         : "r"(rdaddr + 32) : "memory");
            asm volatile("ld.shared.v4.f32 {%0,%1,%2,%3}, [%4];"
                         : "=f"(hvc), "=f"(hvd), "=f"(hve), "=f"(hvf)
                         : "r"(rdaddr + 48) : "memory");

            // ---- f-gate dot FIRST: 4-way split, depth 5 -> af ready ~32cyc
            // into the fma span; its sigma + c-chain hide under i/g/o FFMAs.
            float f0 = fmaf(xv, wxf, bvf);
            float f1 = hv1 * Wf[1];
            float f2 = hv2 * Wf[2];
            float f3 = hv3 * Wf[3];
            f0 = fmaf(hv0, Wf[0],  f0);  f1 = fmaf(hv5, Wf[5],  f1);
            f2 = fmaf(hv6, Wf[6],  f2);  f3 = fmaf(hv7, Wf[7],  f3);
            f0 = fmaf(hv4, Wf[4],  f0);  f1 = fmaf(hv9, Wf[9],  f1);
            f2 = fmaf(hva, Wf[10], f2);  f3 = fmaf(hvb, Wf[11], f3);
            f0 = fmaf(hv8, Wf[8],  f0);  f1 = fmaf(hvd, Wf[13], f1);
            f2 = fmaf(hve, Wf[14], f2);  f3 = fmaf(hvf, Wf[15], f3);
            f0 = fmaf(hvc, Wf[12], f0);
            float af = (f0 + f1) + (f2 + f3);
            float fg = fmaf(0.5f, tanhapx(af), 0.5f);   // hides under i-dot

            // ---- i-gate dot (4-way) ----
            float i0 = fmaf(xv, wxi, bvi);
            float i1 = hv1 * Wi[1];
            float i2 = hv2 * Wi[2];
            float i3 = hv3 * Wi[3];
            i0 = fmaf(hv0, Wi[0],  i0);  i1 = fmaf(hv5, Wi[5],  i1);
            i2 = fmaf(hv6, Wi[6],  i2);  i3 = fmaf(hv7, Wi[7],  i3);
            i0 = fmaf(hv4, Wi[4],  i0);  i1 = fmaf(hv9, Wi[9],  i1);
            i2 = fmaf(hva, Wi[10], i2);  i3 = fmaf(hvb, Wi[11], i3);
            i0 = fmaf(hv8, Wi[8],  i0);  i1 = fmaf(hvd, Wi[13], i1);
            i2 = fmaf(hve, Wi[14], i2);  i3 = fmaf(hvf, Wi[15], i3);
            i0 = fmaf(hvc, Wi[12], i0);
            float ai = (i0 + i1) + (i2 + i3);
            float ig = fmaf(0.5f, tanhapx(ai), 0.5f);   // hides under g-dot

            // ---- g-gate dot (4-way) ----
            float g0 = fmaf(xv, wxg, bvg);
            float g1 = hv1 * Wg[1];
            float g2 = hv2 * Wg[2];
            float g3 = hv3 * Wg[3];
            g0 = fmaf(hv0, Wg[0],  g0);  g1 = fmaf(hv5, Wg[5],  g1);
            g2 = fmaf(hv6, Wg[6],  g2);  g3 = fmaf(hv7, Wg[7],  g3);
            g0 = fmaf(hv4, Wg[4],  g0);  g1 = fmaf(hv9, Wg[9],  g1);
            g2 = fmaf(hva, Wg[10], g2);  g3 = fmaf(hvb, Wg[11], g3);
            g0 = fmaf(hv8, Wg[8],  g0);  g1 = fmaf(hvd, Wg[13], g1);
            g2 = fmaf(hve, Wg[14], g2);  g3 = fmaf(hvf, Wg[15], g3);
            g0 = fmaf(hvc, Wg[12], g0);
            float ag = (g0 + g1) + (g2 + g3);
            float gg = tanhapx(ag);                      // hides under o-dot

            // ---- o-gate dot LAST (its FFMAs overlap the c-chain) ----
            float o0 = fmaf(xv, wxo, bvo);
            float o1 = hv1 * Wo[1];
            float o2 = hv2 * Wo[2];
            float o3 = hv3 * Wo[3];
            o0 = fmaf(hv0, Wo[0],  o0);  o1 = fmaf(hv5, Wo[5],  o1);
            o2 = fmaf(hv6, Wo[6],  o2);  o3 = fmaf(hv7, Wo[7],  o3);
            o0 = fmaf(hv4, Wo[4],  o0);  o1 = fmaf(hv9, Wo[9],  o1);
            o2 = fmaf(hva, Wo[10], o2);  o3 = fmaf(hvb, Wo[11], o3);
            o0 = fmaf(hv8, Wo[8],  o0);  o1 = fmaf(hvd, Wo[13], o1);
            o2 = fmaf(hve, Wo[14], o2);  o3 = fmaf(hvf, Wo[15], o3);
            o0 = fmaf(hvc, Wo[12], o0);

            // c-chain (runs under o's FFMA span)
            c = fmaf(fg, c, ig * gg);
            float tc = tanhapx(c);

            float ao = (o0 + o1) + (o2 + o3);
            float og = fmaf(0.5f, tanhapx(ao), 0.5f);
            h = og * tc;
        }
        // pred = sum_j h_j * W_lin_j + b_lin (feeds xs[15], consumed 15
        // cells later)
        float p = h * wl;
#pragma unroll
        for (int off = 8; off; off >>= 1)
            p += __shfl_xor_sync(FULL, p, off, 16);
        p += bl;

        if (j == 0) outp[t] = p;

#pragma unroll
        for (int s = 0; s < 15; s++) xs[s] = xs[s + 1];
        xs[15] = p;
    }
}

extern "C" void kernel_launch(void* const* d_in, const int* in_sizes, int n_in,
                              void* d_out, int out_size) {
    const float* y     = (const float*)d_in[0];
    const float* u     = (const float*)d_in[1];
    const float* W_ih  = (const float*)d_in[2];
    const float* W_hh  = (const float*)d_in[3];
    const float* b_ih  = (const float*)d_in[4];
    const float* b_hh  = (const float*)d_in[5];
    const float* W_lin = (const float*)d_in[6];
    const float* b_lin = (const float*)d_in[7];
    const float* W_h0  = (const float*)d_in[8];
    const float* b_h0  = (const float*)d_in[9];
    const float* W_c0  = (const float*)d_in[10];
    const float* b_c0  = (const float*)d_in[11];
    float* out = (float*)d_out;

    // 128 blocks x 128 threads = 512 warps, 1/SMSP (validated optimal spread)
    lstm_decoder_kernel<<<128, 128>>>(y, u, W_ih, W_hh, b_ih, b_hh,
                                      W_lin, b_lin, W_h0, b_h0, W_c0, b_c0, out);
}